// round 9
// baseline (speedup 1.0000x reference)
#include <cuda_runtime.h>
#include <cuda_bf16.h>
#include <cooperative_groups.h>

namespace cg = cooperative_groups;

// Problem constants (pinned by the reference)
#define B_DIM   64
#define S_DIM   8192
#define D_DIM   64
#define N_BINS  256                 // output bins; bin 256 = dummy (T >= 256)
#define NCHUNK  4                   // CTAs (cluster size) per batch in the sort
#define CHUNK_S (S_DIM / NCHUNK)    // 2048 tokens per chunk
#define NBIN1   (N_BINS + 1)        // 257 (incl. dummy)
#define STARTS_PER_B 258

// Scratch (allocation-free rule: __device__ globals)
__device__ int2 g_sorted[B_DIM * S_DIM];          // (x, w-bits), bin-contiguous per batch
__device__ int  g_start [B_DIM * STARTS_PER_B];   // per-batch exclusive bin starts

// ---------------------------------------------------------------------------
// K1: fused per-batch counting sort with SMEM-STAGED (coalesced) output.
// 64 clusters x 4 CTAs, 512 threads/CTA.  (unchanged from R8: ~4.1 us)
// ---------------------------------------------------------------------------
__global__ __launch_bounds__(512, 2) __cluster_dims__(NCHUNK, 1, 1)
void k_sort(const float* __restrict__ T, const int* __restrict__ X,
            const float* __restrict__ embedW)
{
    __shared__ int            hist [NBIN1];
    __shared__ int            scanT[NBIN1];   // batch-wide totals (scanned)
    __shared__ int            scanL[NBIN1];   // own-chunk hist (scanned)
    __shared__ int            delta[NBIN1];   // p_local + delta[bin] = global pos
    __shared__ int            loffs[NBIN1];   // local scatter cursors
    __shared__ unsigned short sbin [CHUNK_S]; // bin at original position
    __shared__ unsigned short sbin2[CHUNK_S]; // bin at locally-sorted position
    __shared__ int            sx   [CHUNK_S]; // token id at locally-sorted position

    cg::cluster_group cluster = cg::this_cluster();
    const int c   = (int)cluster.block_rank();     // chunk 0..3
    const int b   = blockIdx.x >> 2;               // batch
    const int tid = threadIdx.x;

    for (int i = tid; i < NBIN1; i += 512) hist[i] = 0;
    __syncthreads();

    // --- A: bin + local histogram ---
    const float* Tb = T + b * S_DIM + c * CHUNK_S;
    #pragma unroll 4
    for (int s = tid; s < CHUNK_S; s += 512) {
        float t = Tb[s];
        int bin = (t < 256.0f) ? (int)t : N_BINS;  // t >= 0 -> (int)t == floor
        sbin[s] = (unsigned short)bin;
        atomicAdd(&hist[bin], 1);
    }
    cluster.sync();

    // --- B: peer hist gather + dual scan ---
    int tot = 0, part = 0, own = 0;
    if (tid < NBIN1) {
        #pragma unroll
        for (int cc = 0; cc < NCHUNK; ++cc) {
            const int* rh = cluster.map_shared_rank(hist, cc);
            int h = rh[tid];
            tot += h;
            if (cc < c) part += h;
        }
        own = hist[tid];
        scanT[tid] = tot;
        scanL[tid] = own;
    }
    __syncthreads();

    for (int d = 1; d < NBIN1; d <<= 1) {
        int vT = 0, vL = 0;
        if (tid < NBIN1 && tid >= d) { vT = scanT[tid - d]; vL = scanL[tid - d]; }
        __syncthreads();
        if (tid < NBIN1) { scanT[tid] += vT; scanL[tid] += vL; }
        __syncthreads();
    }

    if (tid < NBIN1) {
        int gbase = scanT[tid] - tot;   // batch-wide bin start
        int lbase = scanL[tid] - own;   // local (chunk) bin start
        loffs[tid] = lbase;
        delta[tid] = gbase + part - lbase;
        if (c == 0) {
            g_start[b * STARTS_PER_B + tid] = gbase;
            if (tid == 0) g_start[b * STARTS_PER_B + NBIN1] = S_DIM;
        }
    }
    __syncthreads();

    // --- C: local scatter into smem (bin-contiguous within chunk) ---
    const int* Xb = X + b * S_DIM + c * CHUNK_S;
    #pragma unroll 4
    for (int s = tid; s < CHUNK_S; s += 512) {
        int bin  = sbin[s];
        int lpos = atomicAdd(&loffs[bin], 1);
        sx[lpos]    = Xb[s];
        sbin2[lpos] = (unsigned short)bin;
    }
    __syncthreads();

    // --- D: coalesced copy-out + weight compute ---
    int2* dst = g_sorted + b * S_DIM;
    #pragma unroll 4
    for (int p = tid; p < CHUNK_S; p += 512) {
        int   x   = sx[p];
        int   bin = sbin2[p];
        float w   = __expf(__ldg(&embedW[x]));
        dst[p + delta[bin]] = make_int2(x, __float_as_int(w));
    }

    cluster.sync();   // peers may still be reading our smem hist
}

// ---------------------------------------------------------------------------
// K2: one warp per (batch, bin). Lane l owns output dims {2l, 2l+1} (float2).
// Coalesced 256B (x,w) block loads + __shfl distribution, EXACT-COUNT
// execution:
//   * full 32-token blocks: unrolled, no checks
//   * one remainder block: warp-UNIFORM `if (j >= rem) break` inside the
//     unrolled loop (s0/s1 uniform across the warp -> convergent shuffles),
//     so no dummy x=0 gathers. This removes the ~46% padded-gather waste
//     (E[ceil(n/32)] = 1.46 blocks for Poisson(32) bins).
// launch_bounds(256,6): 32-42 reg class keeps ~48 warps/SM resident.
// ---------------------------------------------------------------------------
__global__ __launch_bounds__(256, 6)
void k_bin_reduce(const float* __restrict__ embedX, float* __restrict__ out)
{
    const int warp = (blockIdx.x * blockDim.x + threadIdx.x) >> 5;  // 0..16383
    const int lane = threadIdx.x & 31;
    const int b    = warp >> 8;
    const int bin  = warp & 255;

    const int* gs = g_start + b * STARTS_PER_B;
    const int  s0 = gs[bin];
    const int  s1 = gs[bin + 1];
    const int  n  = s1 - s0;

    const int2*   sxw = g_sorted + b * S_DIM + s0;
    const float2* ex  = reinterpret_cast<const float2*>(embedX);

    float2 acc = make_float2(0.0f, 0.0f);

    int base = 0;
    // full 32-token blocks: no per-iteration checks
    for (; base + 32 <= n; base += 32) {
        int2 xw = __ldg(&sxw[base + lane]);
        #pragma unroll
        for (int j = 0; j < 32; ++j) {
            int   x = __shfl_sync(0xffffffffu, xw.x, j);
            float w = __int_as_float(__shfl_sync(0xffffffffu, xw.y, j));
            float2 e = __ldg(&ex[x * 32 + lane]);
            acc.x = fmaf(w, e.x, acc.x);
            acc.y = fmaf(w, e.y, acc.y);
        }
    }

    // remainder block: exact count via warp-uniform break
    int rem = n - base;
    if (rem > 0) {
        int  idx = base + lane;
        int2 xw  = (lane < rem) ? __ldg(&sxw[idx]) : make_int2(0, 0);
        #pragma unroll
        for (int j = 0; j < 32; ++j) {
            if (j >= rem) break;                     // uniform across warp
            int   x = __shfl_sync(0xffffffffu, xw.x, j);
            float w = __int_as_float(__shfl_sync(0xffffffffu, xw.y, j));
            float2 e = __ldg(&ex[x * 32 + lane]);
            acc.x = fmaf(w, e.x, acc.x);
            acc.y = fmaf(w, e.y, acc.y);
        }
    }

    float inv = 1.0f / ((float)n + 1e-6f);
    reinterpret_cast<float2*>(out)[(b * N_BINS + bin) * 32 + lane] =
        make_float2(acc.x * inv, acc.y * inv);
}

// ---------------------------------------------------------------------------
// Inputs (metadata order):
//   d_in[0] : T        float32 [B, S]
//   d_in[1] : X_ids    int32   [B, S]
//   d_in[2] : embedX_w float32 [N_TOKENS+1, 64]
//   d_in[3] : embedW_w float32 [N_TOKENS+1, 1]
// Output    : float32 [B, 256, 64]
// ---------------------------------------------------------------------------
extern "C" void kernel_launch(void* const* d_in, const int* in_sizes, int n_in,
                              void* d_out, int out_size)
{
    const float* T      = (const float*)d_in[0];
    const int*   X_ids  = (const int*)  d_in[1];
    const float* embedX = (const float*)d_in[2];
    const float* embedW = (const float*)d_in[3];
    float*       out    = (float*)d_out;

    k_sort      <<<B_DIM * NCHUNK, 512>>>(T, X_ids, embedW);
    k_bin_reduce<<<(B_DIM * N_BINS) / 8, 256>>>(embedX, out);
}

// round 10
// speedup vs baseline: 1.4562x; 1.4562x over previous
#include <cuda_runtime.h>
#include <cuda_bf16.h>
#include <cooperative_groups.h>

namespace cg = cooperative_groups;

// Problem constants (pinned by the reference)
#define B_DIM   64
#define S_DIM   8192
#define D_DIM   64
#define N_BINS  256                 // output bins; bin 256 = dummy (T >= 256)
#define NCHUNK  4                   // CTAs (cluster size) per batch in the sort
#define CHUNK_S (S_DIM / NCHUNK)    // 2048 tokens per chunk
#define NBIN1   (N_BINS + 1)        // 257 (incl. dummy)
#define STARTS_PER_B 258

#define BINS_PER_CTA 8              // K2: one warp per bin, 8 bins per CTA
#define STAGE_CAP    1024           // smem (x,w) slots per CTA (8 KB); E[need]=256

// Scratch (allocation-free rule: __device__ globals)
__device__ int2 g_sorted[B_DIM * S_DIM];          // (x, w-bits), bin-contiguous per batch
__device__ int  g_start [B_DIM * STARTS_PER_B];   // per-batch exclusive bin starts

// ---------------------------------------------------------------------------
// K1: fused per-batch counting sort with SMEM-STAGED (coalesced) output.
// 64 clusters x 4 CTAs, 512 threads/CTA.  (frozen since R8: ~3.8-4.1 us)
// ---------------------------------------------------------------------------
__global__ __launch_bounds__(512, 2) __cluster_dims__(NCHUNK, 1, 1)
void k_sort(const float* __restrict__ T, const int* __restrict__ X,
            const float* __restrict__ embedW)
{
    __shared__ int            hist [NBIN1];
    __shared__ int            scanT[NBIN1];   // batch-wide totals (scanned)
    __shared__ int            scanL[NBIN1];   // own-chunk hist (scanned)
    __shared__ int            delta[NBIN1];   // p_local + delta[bin] = global pos
    __shared__ int            loffs[NBIN1];   // local scatter cursors
    __shared__ unsigned short sbin [CHUNK_S]; // bin at original position
    __shared__ unsigned short sbin2[CHUNK_S]; // bin at locally-sorted position
    __shared__ int            sx   [CHUNK_S]; // token id at locally-sorted position

    cg::cluster_group cluster = cg::this_cluster();
    const int c   = (int)cluster.block_rank();     // chunk 0..3
    const int b   = blockIdx.x >> 2;               // batch
    const int tid = threadIdx.x;

    for (int i = tid; i < NBIN1; i += 512) hist[i] = 0;
    __syncthreads();

    // --- A: bin + local histogram ---
    const float* Tb = T + b * S_DIM + c * CHUNK_S;
    #pragma unroll 4
    for (int s = tid; s < CHUNK_S; s += 512) {
        float t = Tb[s];
        int bin = (t < 256.0f) ? (int)t : N_BINS;  // t >= 0 -> (int)t == floor
        sbin[s] = (unsigned short)bin;
        atomicAdd(&hist[bin], 1);
    }
    cluster.sync();

    // --- B: peer hist gather + dual scan ---
    int tot = 0, part = 0, own = 0;
    if (tid < NBIN1) {
        #pragma unroll
        for (int cc = 0; cc < NCHUNK; ++cc) {
            const int* rh = cluster.map_shared_rank(hist, cc);
            int h = rh[tid];
            tot += h;
            if (cc < c) part += h;
        }
        own = hist[tid];
        scanT[tid] = tot;
        scanL[tid] = own;
    }
    __syncthreads();

    for (int d = 1; d < NBIN1; d <<= 1) {
        int vT = 0, vL = 0;
        if (tid < NBIN1 && tid >= d) { vT = scanT[tid - d]; vL = scanL[tid - d]; }
        __syncthreads();
        if (tid < NBIN1) { scanT[tid] += vT; scanL[tid] += vL; }
        __syncthreads();
    }

    if (tid < NBIN1) {
        int gbase = scanT[tid] - tot;   // batch-wide bin start
        int lbase = scanL[tid] - own;   // local (chunk) bin start
        loffs[tid] = lbase;
        delta[tid] = gbase + part - lbase;
        if (c == 0) {
            g_start[b * STARTS_PER_B + tid] = gbase;
            if (tid == 0) g_start[b * STARTS_PER_B + NBIN1] = S_DIM;
        }
    }
    __syncthreads();

    // --- C: local scatter into smem (bin-contiguous within chunk) ---
    const int* Xb = X + b * S_DIM + c * CHUNK_S;
    #pragma unroll 4
    for (int s = tid; s < CHUNK_S; s += 512) {
        int bin  = sbin[s];
        int lpos = atomicAdd(&loffs[bin], 1);
        sx[lpos]    = Xb[s];
        sbin2[lpos] = (unsigned short)bin;
    }
    __syncthreads();

    // --- D: coalesced copy-out + weight compute ---
    int2* dst = g_sorted + b * S_DIM;
    #pragma unroll 4
    for (int p = tid; p < CHUNK_S; p += 512) {
        int   x   = sx[p];
        int   bin = sbin2[p];
        float w   = __expf(__ldg(&embedW[x]));
        dst[p + delta[bin]] = make_int2(x, __float_as_int(w));
    }

    cluster.sync();   // peers may still be reading our smem hist
}

// ---------------------------------------------------------------------------
// K2: one CTA per (batch, 8 consecutive bins); one warp per bin.
// The CTA's token range [gs[bin0], gs[bin0+8]) is CONTIGUOUS in g_sorted:
// cooperatively copy it (coalesced) into smem once. Each warp then walks its
// bin with an EXACT trip count:
//     LDS.64 broadcast (x,w)  ->  LDG.64 float2 row gather  ->  2 FFMA
// No shuffles (no convergence constraint -> plain unroll-4 loop, zero padded
// gathers: 134 MB exact L2 traffic), no dependent block-header load.
// Fallback: if the 8-bin group exceeds STAGE_CAP tokens (never for this
// input's Poisson(256) groups), warps read (x,w) directly via broadcast LDG.
// ---------------------------------------------------------------------------
__global__ __launch_bounds__(256)
void k_bin_reduce(const float* __restrict__ embedX, float* __restrict__ out)
{
    __shared__ int2 stage[STAGE_CAP];
    __shared__ int  sgs[BINS_PER_CTA + 1];

    const int tid  = threadIdx.x;
    const int wid  = tid >> 5;                 // warp in CTA = bin offset 0..7
    const int lane = tid & 31;
    const int b    = blockIdx.x >> 5;          // batch 0..63
    const int bin0 = (blockIdx.x & 31) * BINS_PER_CTA;

    if (tid <= BINS_PER_CTA)
        sgs[tid] = g_start[b * STARTS_PER_B + bin0 + tid];
    __syncthreads();

    const int s0c = sgs[0];
    const int cnt = sgs[BINS_PER_CTA] - s0c;
    const int2* gxw = g_sorted + b * S_DIM + s0c;

    const bool staged = (cnt <= STAGE_CAP);
    if (staged) {
        for (int i = tid; i < cnt; i += 256)
            stage[i] = gxw[i];
    }
    __syncthreads();

    const int s0 = sgs[wid]     - s0c;         // this warp's bin, local offsets
    const int s1 = sgs[wid + 1] - s0c;
    const int n  = s1 - s0;

    const float2* ex = reinterpret_cast<const float2*>(embedX);
    float2 acc = make_float2(0.0f, 0.0f);

    if (staged) {
        #pragma unroll 4
        for (int i = s0; i < s1; ++i) {
            int2  xw = stage[i];               // broadcast LDS.64
            float w  = __int_as_float(xw.y);
            float2 e = __ldg(&ex[xw.x * 32 + lane]);
            acc.x = fmaf(w, e.x, acc.x);
            acc.y = fmaf(w, e.y, acc.y);
        }
    } else {
        #pragma unroll 4
        for (int i = s0; i < s1; ++i) {
            int2  xw = __ldg(&gxw[i]);         // broadcast LDG.64
            float w  = __int_as_float(xw.y);
            float2 e = __ldg(&ex[xw.x * 32 + lane]);
            acc.x = fmaf(w, e.x, acc.x);
            acc.y = fmaf(w, e.y, acc.y);
        }
    }

    float inv = 1.0f / ((float)n + 1e-6f);
    reinterpret_cast<float2*>(out)[(b * N_BINS + bin0 + wid) * 32 + lane] =
        make_float2(acc.x * inv, acc.y * inv);
}

// ---------------------------------------------------------------------------
// Inputs (metadata order):
//   d_in[0] : T        float32 [B, S]
//   d_in[1] : X_ids    int32   [B, S]
//   d_in[2] : embedX_w float32 [N_TOKENS+1, 64]
//   d_in[3] : embedW_w float32 [N_TOKENS+1, 1]
// Output    : float32 [B, 256, 64]
// ---------------------------------------------------------------------------
extern "C" void kernel_launch(void* const* d_in, const int* in_sizes, int n_in,
                              void* d_out, int out_size)
{
    const float* T      = (const float*)d_in[0];
    const int*   X_ids  = (const int*)  d_in[1];
    const float* embedX = (const float*)d_in[2];
    const float* embedW = (const float*)d_in[3];
    float*       out    = (float*)d_out;

    k_sort      <<<B_DIM * NCHUNK, 512>>>(T, X_ids, embedW);
    k_bin_reduce<<<B_DIM * (N_BINS / BINS_PER_CTA), 256>>>(embedX, out);
}